// round 11
// baseline (speedup 1.0000x reference)
#include <cuda_runtime.h>
#include <math.h>

#define BB   1024
#define NN   40
#define ETAD 64
#define KK   32
#define ZDIM 32
#define NA   10
#define NB   5
#define CH   128
#define AH   128
#define BH   64
#define NODES (BB*NN)        /* 40960 */
#define EPB   780            /* C(40,2) edges per batch */
#define ZPAD  36             /* padded row stride (floats), 16B aligned */

/* ---- scratch (static device memory; allocation-free) ---- */
__device__ __align__(16) float g_s[BB*KK];
__device__ __align__(16) float g_z[NODES*ZDIM];
__device__ __align__(16) float g_wsym[NB*ZDIM*ZDIM];
__device__ __align__(16) float g_w2t[NB*BH];          /* bW2 transposed [t][j] */
__device__ __align__(16) float g_small[40];           /* [0..24]=wss, [28..32]=bb2+bbs */

/* ---- HOT edge-MLP weights: SEPARATE constant symbols (R7/R10-proven).
   Packing them into one array defeats ptxas's LDCU uniform-promotion
   (LDC GPR-dest floor=8 vs LDCU floor=1) and doubles k_edge. Keep split. ---- */
__constant__ __align__(16) float c_bW1[NB*BH];        /* [t][j] raw            */
__constant__ __align__(16) float c_w2t[NB*BH];        /* transposed [t][j]     */
__constant__ __align__(16) float c_bb1[BH];

/* ---- f32x2 packed helpers (sm_100+) ---- */
__device__ __forceinline__ unsigned long long pk2(float lo, float hi) {
    unsigned long long r;
    asm("mov.b64 %0, {%1, %2};" : "=l"(r) : "f"(lo), "f"(hi));
    return r;
}
__device__ __forceinline__ void upk2(unsigned long long v, float& lo, float& hi) {
    asm("mov.b64 {%0, %1}, %2;" : "=f"(lo), "=f"(hi) : "l"(v));
}
__device__ __forceinline__ unsigned long long fma2(unsigned long long a,
                                                   unsigned long long b,
                                                   unsigned long long c) {
    unsigned long long r;
    asm("fma.rn.f32x2 %0, %1, %2, %3;" : "=l"(r) : "l"(a), "l"(b), "l"(c));
    return r;
}

/* lex-order edge index for pair (i<j) in a batch of NN nodes */
__device__ __forceinline__ int eidx(int i, int j) {
    return i*(2*NN - 1 - i)/2 + (j - i - 1);
}

/* -------- kernel 0: fused prep + cluster logits (2 batches/block) --------
   blocks 0..511  : cluster resblock for batches 2b, 2b+1 (shared W loads)
   blocks 512..531: Wsym symmetrize + bW2 transpose + g_small pack        */
__global__ void k_prep_cluster(const float* __restrict__ bm, const float* __restrict__ bW2,
                               const float* __restrict__ bWs, const float* __restrict__ bb2,
                               const float* __restrict__ bbs,
                               const float* __restrict__ eta,
                               const float* __restrict__ cW1, const float* __restrict__ cb1,
                               const float* __restrict__ cW2, const float* __restrict__ cb2,
                               const float* __restrict__ cWs, const float* __restrict__ cbs) {
    int tid = threadIdx.x;
    if (blockIdx.x >= BB/2) {
        int base = (blockIdx.x - BB/2) * CH;
        for (int i = base + tid; i < NB*ZDIM*ZDIM; i += 20*CH) {
            int t = i / (ZDIM*ZDIM);
            int r = (i / ZDIM) % ZDIM;
            int c = i % ZDIM;
            g_wsym[i] = 0.5f * (bm[t*ZDIM*ZDIM + r*ZDIM + c] +
                                bm[t*ZDIM*ZDIM + c*ZDIM + r]);
        }
        for (int i = base + tid; i < NB*BH; i += 20*CH) {
            int t = i >> 6, j = i & 63;
            g_w2t[i] = bW2[j*NB + t];
        }
        if (blockIdx.x == BB/2) {
            if (tid < NB*NB) g_small[tid] = bWs[tid];
            if (tid < NB)    g_small[28 + tid] = bb2[tid] + bbs[tid];
        }
        return;
    }
    __shared__ float etaA[ETAD], etaB[ETAD];
    __shared__ float hA[CH], hB[CH];
    int b0 = blockIdx.x * 2, b1 = b0 + 1;
    if (tid < ETAD) etaA[tid] = eta[b0*ETAD + tid];
    else            etaB[tid - ETAD] = eta[b1*ETAD + (tid - ETAD)];
    __syncthreads();
    float aA = cb1[tid], aB = aA;
    #pragma unroll 16
    for (int e = 0; e < ETAD; e++) {
        float w = cW1[e*CH + tid];
        aA = fmaf(etaA[e], w, aA);
        aB = fmaf(etaB[e], w, aB);
    }
    hA[tid] = fmaxf(aA, 0.f);
    hB[tid] = fmaxf(aB, 0.f);
    __syncthreads();
    if (tid < KK) {
        float sA = cb2[tid] + cbs[tid], sB = sA;
        #pragma unroll 16
        for (int j = 0; j < CH; j++) {
            float w = cW2[j*KK + tid];
            sA = fmaf(hA[j], w, sA);
            sB = fmaf(hB[j], w, sB);
        }
        #pragma unroll 16
        for (int e = 0; e < ETAD; e++) {
            float w = cWs[e*KK + tid];
            sA = fmaf(etaA[e], w, sA);
            sB = fmaf(etaB[e], w, sB);
        }
        g_s[b0*KK + tid] = sA;
        g_s[b1*KK + tid] = sB;
    }
}

/* -------- kernel 1: warp handles 4 nodes; weights reused across nodes -------- */
__global__ __launch_bounds__(256)
void k_node(const float* __restrict__ gum, const float* __restrict__ zn,
            const float* __restrict__ cm,  const float* __restrict__ cls,
            const float* __restrict__ aW1, const float* __restrict__ ab1,
            const float* __restrict__ aW2, const float* __restrict__ ab2,
            const float* __restrict__ aWs, const float* __restrict__ absk,
            float* __restrict__ atom_out) {
    __shared__ float4 w1s4[ZDIM*32];
    __shared__ __align__(16) float aw2t[NA*AH];
    __shared__ __align__(16) float awst[NA*ZDIM];
    __shared__ float4 ab1s4[32];
    __shared__ float  ab2s[NA];
    __shared__ __align__(16) float zsm[8][4][ZDIM];
    __shared__ __align__(16) float hsm[8][4][AH];

    int tid  = threadIdx.x;
    int warp = tid >> 5;
    int lane = tid & 31;

    for (int i = tid; i < ZDIM*32; i += 256) w1s4[i] = ((const float4*)aW1)[i];
    for (int i = tid; i < NA*AH;  i += 256) { int o = i / AH, j = i % AH; aw2t[i] = aW2[j*NA + o]; }
    for (int i = tid; i < NA*ZDIM; i += 256) { int o = i / ZDIM, d = i % ZDIM; awst[i] = aWs[d*NA + o]; }
    if (tid < 32) ab1s4[tid] = ((const float4*)ab1)[tid];
    if (tid < NA) ab2s[tid]  = ab2[tid] + absk[tid];
    __syncthreads();

    int node0 = blockIdx.x * 32 + warp;

    #pragma unroll
    for (int u = 0; u < 4; u++) {
        int node = node0 + u*8;
        int b = (unsigned)node / NN;
        float val = g_s[b*KK + lane] + gum[node*KK + lane];
        int idx = lane;
        #pragma unroll
        for (int off = 16; off; off >>= 1) {
            float ov = __shfl_xor_sync(0xffffffffu, val, off);
            int   oi = __shfl_xor_sync(0xffffffffu, idx, off);
            if (ov > val || (ov == val && oi < idx)) { val = ov; idx = oi; }
        }
        int kmax = idx;
        float ls = cls[kmax*ZDIM + lane];
        float sg = __expf(fminf(fmaxf(ls, -20.f), 30.f));
        float z  = fmaf(zn[node*ZDIM + lane], sg, cm[kmax*ZDIM + lane]);
        g_z[node*ZDIM + lane] = z;
        zsm[warp][u][lane] = z;
    }
    __syncwarp();

    float4 acc0 = ab1s4[lane], acc1 = acc0, acc2 = acc0, acc3 = acc0;
    #pragma unroll
    for (int d = 0; d < ZDIM; d++) {
        float4 w = w1s4[d*32 + lane];
        float z0 = zsm[warp][0][d], z1 = zsm[warp][1][d];
        float z2 = zsm[warp][2][d], z3 = zsm[warp][3][d];
        acc0.x = fmaf(z0, w.x, acc0.x); acc0.y = fmaf(z0, w.y, acc0.y);
        acc0.z = fmaf(z0, w.z, acc0.z); acc0.w = fmaf(z0, w.w, acc0.w);
        acc1.x = fmaf(z1, w.x, acc1.x); acc1.y = fmaf(z1, w.y, acc1.y);
        acc1.z = fmaf(z1, w.z, acc1.z); acc1.w = fmaf(z1, w.w, acc1.w);
        acc2.x = fmaf(z2, w.x, acc2.x); acc2.y = fmaf(z2, w.y, acc2.y);
        acc2.z = fmaf(z2, w.z, acc2.z); acc2.w = fmaf(z2, w.w, acc2.w);
        acc3.x = fmaf(z3, w.x, acc3.x); acc3.y = fmaf(z3, w.y, acc3.y);
        acc3.z = fmaf(z3, w.z, acc3.z); acc3.w = fmaf(z3, w.w, acc3.w);
    }
    #define RELU4(a) { a.x=fmaxf(a.x,0.f); a.y=fmaxf(a.y,0.f); a.z=fmaxf(a.z,0.f); a.w=fmaxf(a.w,0.f); }
    RELU4(acc0) RELU4(acc1) RELU4(acc2) RELU4(acc3)
    reinterpret_cast<float4*>(hsm[warp][0])[lane] = acc0;
    reinterpret_cast<float4*>(hsm[warp][1])[lane] = acc1;
    reinterpret_cast<float4*>(hsm[warp][2])[lane] = acc2;
    reinterpret_cast<float4*>(hsm[warp][3])[lane] = acc3;
    __syncwarp();

    #pragma unroll
    for (int pass = 0; pass < 2; pass++) {
        int q = pass*32 + lane;
        if (q < 40) {
            int u = q / 10, o = q % 10;
            float s = ab2s[o];
            #pragma unroll 8
            for (int j4 = 0; j4 < AH/4; j4++) {
                float4 h = *reinterpret_cast<const float4*>(&hsm[warp][u][j4*4]);
                float4 w = *reinterpret_cast<const float4*>(&aw2t[o*AH + j4*4]);
                s = fmaf(h.x, w.x, fmaf(h.y, w.y, fmaf(h.z, w.z, fmaf(h.w, w.w, s))));
            }
            #pragma unroll
            for (int d4 = 0; d4 < ZDIM/4; d4++) {
                float4 zv = *reinterpret_cast<const float4*>(&zsm[warp][u][d4*4]);
                float4 w  = *reinterpret_cast<const float4*>(&awst[o*ZDIM + d4*4]);
                s = fmaf(zv.x, w.x, fmaf(zv.y, w.y, fmaf(zv.z, w.z, fmaf(zv.w, w.w, s))));
            }
            atom_out[(node0 + u*8)*NA + o] = s;
        }
    }
}

/* -------- kernel 2: edges; (i0,i1|j) tiles, constant weights, f32x2 MLP ---- */
__global__ __launch_bounds__(256, 3)
void k_edge(float* __restrict__ edge_out) {
    __shared__ __align__(16) float zs[NN*ZPAD];
    __shared__ __align__(16) float vs[NB*NN*ZPAD];

    int b   = blockIdx.x;
    int tid = threadIdx.x;

    for (int i = tid; i < NN*8; i += 256) {
        int n = i >> 3, d4 = i & 7;
        *reinterpret_cast<float4*>(&zs[n*ZPAD + d4*4]) =
            reinterpret_cast<const float4*>(g_z)[(size_t)b*NN*8 + i];
    }
    __syncthreads();

    /* v[t][j][d] = sum_c Wsym[t][c][d] * z[j][c] */
    for (int base = 0; base < NN*8; base += 256) {
        int idx = base + tid;
        if (idx < NN*8) {
            int j = idx >> 3, d4 = idx & 7;
            #pragma unroll
            for (int t = 0; t < NB; t++) {
                float4 acc = make_float4(0.f, 0.f, 0.f, 0.f);
                const float4* W = reinterpret_cast<const float4*>(g_wsym) + t*256 + d4;
                #pragma unroll 8
                for (int c = 0; c < ZDIM; c++) {
                    float zc = zs[j*ZPAD + c];
                    float4 w = W[c*8];
                    acc.x = fmaf(zc, w.x, acc.x);
                    acc.y = fmaf(zc, w.y, acc.y);
                    acc.z = fmaf(zc, w.z, acc.z);
                    acc.w = fmaf(zc, w.w, acc.w);
                }
                *reinterpret_cast<float4*>(&vs[t*NN*ZPAD + j*ZPAD + d4*4]) = acc;
            }
        }
    }
    __syncthreads();

    float* outb = edge_out + (size_t)b * EPB * NB;

    for (int w = tid; w < 400; w += 256) {
        int i0, i1, j;
        if (w < 380) {
            int I = (int)(19.5f - sqrtf(380.25f - (float)w));
            if (I > 18) I = 18;
            if (I < 0)  I = 0;
            int c = I*(39 - I);
            if (w < c)  { I--; c = I*(39 - I); }
            else        { int c2 = (I + 1)*(38 - I); if (w >= c2) { I++; c = c2; } }
            j  = 2*I + 2 + (w - c);
            i0 = 2*I; i1 = 2*I + 1;
        } else {
            int I = w - 380;
            i0 = 2*I; i1 = 2*I; j = 2*I + 1;
        }
        int e0 = eidx(i0, j), e1 = eidx(i1, j);

        /* bilinear: v row shared across both edges */
        float bil0[NB], bil1[NB];
        #pragma unroll
        for (int t = 0; t < NB; t++) { bil0[t] = 0.f; bil1[t] = 0.f; }
        #pragma unroll
        for (int d4 = 0; d4 < 8; d4++) {
            float4 z0 = *reinterpret_cast<const float4*>(&zs[i0*ZPAD + d4*4]);
            float4 z1 = *reinterpret_cast<const float4*>(&zs[i1*ZPAD + d4*4]);
            #pragma unroll
            for (int t = 0; t < NB; t++) {
                float4 v = *reinterpret_cast<const float4*>(&vs[t*NN*ZPAD + j*ZPAD + d4*4]);
                bil0[t] = fmaf(z0.w, v.w, fmaf(z0.z, v.z, fmaf(z0.y, v.y, fmaf(z0.x, v.x, bil0[t]))));
                bil1[t] = fmaf(z1.w, v.w, fmaf(z1.z, v.z, fmaf(z1.y, v.y, fmaf(z1.x, v.x, bil1[t]))));
            }
        }

        /* skip path (cold weights via uniform global loads) + pack */
        unsigned long long oo0[NB], oo1[NB], bp0[NB], bp1[NB];
        #pragma unroll
        for (int t = 0; t < NB; t++) {
            float base = __ldg(&g_small[28 + t]);     /* bb2 + bbs pre-summed */
            float s0 = base, s1 = base;
            #pragma unroll
            for (int u = 0; u < NB; u++) {
                float wv = __ldg(&g_small[u*NB + t]); /* wss */
                s0 = fmaf(bil0[u], wv, s0);
                s1 = fmaf(bil1[u], wv, s1);
            }
            oo0[t] = pk2(s0, 0.f);
            oo1[t] = pk2(s1, 0.f);
            bp0[t] = pk2(bil0[t], bil0[t]);
            bp1[t] = pk2(bil1[t], bil1[t]);
        }

        /* MLP: hidden pairs, weights via uniform constant (LDCU) loads */
        #pragma unroll 4
        for (int jp = 0; jp < BH/2; jp++) {
            unsigned long long b1p =
                *reinterpret_cast<const unsigned long long*>(&c_bb1[2*jp]);
            unsigned long long h0 = b1p, h1 = b1p;
            #pragma unroll
            for (int t = 0; t < NB; t++) {
                unsigned long long w1p =
                    *reinterpret_cast<const unsigned long long*>(&c_bW1[t*BH + 2*jp]);
                h0 = fma2(bp0[t], w1p, h0);
                h1 = fma2(bp1[t], w1p, h1);
            }
            { float x, y; upk2(h0, x, y); h0 = pk2(fmaxf(x, 0.f), fmaxf(y, 0.f)); }
            { float x, y; upk2(h1, x, y); h1 = pk2(fmaxf(x, 0.f), fmaxf(y, 0.f)); }
            #pragma unroll
            for (int t = 0; t < NB; t++) {
                unsigned long long w2p =
                    *reinterpret_cast<const unsigned long long*>(&c_w2t[t*BH + 2*jp]);
                oo0[t] = fma2(h0, w2p, oo0[t]);
                oo1[t] = fma2(h1, w2p, oo1[t]);
            }
        }

        /* reduce halves, softmax, store */
        {
            float o[NB];
            #pragma unroll
            for (int t = 0; t < NB; t++) { float x, y; upk2(oo0[t], x, y); o[t] = x + y; }
            float m = o[0];
            #pragma unroll
            for (int t = 1; t < NB; t++) m = fmaxf(m, o[t]);
            float s = 0.f, ex[NB];
            #pragma unroll
            for (int t = 0; t < NB; t++) { ex[t] = __expf(o[t] - m); s += ex[t]; }
            float inv = __fdividef(1.f, s);
            #pragma unroll
            for (int t = 0; t < NB; t++) outb[e0*NB + t] = ex[t] * inv;
        }
        {
            float o[NB];
            #pragma unroll
            for (int t = 0; t < NB; t++) { float x, y; upk2(oo1[t], x, y); o[t] = x + y; }
            float m = o[0];
            #pragma unroll
            for (int t = 1; t < NB; t++) m = fmaxf(m, o[t]);
            float s = 0.f, ex[NB];
            #pragma unroll
            for (int t = 0; t < NB; t++) { ex[t] = __expf(o[t] - m); s += ex[t]; }
            float inv = __fdividef(1.f, s);
            #pragma unroll
            for (int t = 0; t < NB; t++) outb[e1*NB + t] = ex[t] * inv;
        }
    }
}

/* ------------------------- launch ------------------------- */
extern "C" void kernel_launch(void* const* d_in, const int* in_sizes, int n_in,
                              void* d_out, int out_size) {
    const float* eta  = (const float*)d_in[0];
    const float* gum  = (const float*)d_in[1];
    const float* zn   = (const float*)d_in[2];
    const float* cW1  = (const float*)d_in[3];
    const float* cb1  = (const float*)d_in[4];
    const float* cW2  = (const float*)d_in[5];
    const float* cb2  = (const float*)d_in[6];
    const float* cWs  = (const float*)d_in[7];
    const float* cbs  = (const float*)d_in[8];
    const float* cm   = (const float*)d_in[9];
    const float* cls  = (const float*)d_in[10];
    const float* aW1  = (const float*)d_in[11];
    const float* ab1  = (const float*)d_in[12];
    const float* aW2  = (const float*)d_in[13];
    const float* ab2  = (const float*)d_in[14];
    const float* aWs  = (const float*)d_in[15];
    const float* absk = (const float*)d_in[16];
    const float* bm   = (const float*)d_in[17];
    const float* bW1  = (const float*)d_in[18];
    const float* bb1  = (const float*)d_in[19];
    const float* bW2  = (const float*)d_in[20];
    const float* bb2  = (const float*)d_in[21];
    const float* bWs  = (const float*)d_in[22];
    const float* bbs  = (const float*)d_in[23];

    float* atom_out = (float*)d_out;
    float* edge_out = atom_out + (size_t)NODES * NA;

    /* hot edge-MLP weights -> separate constant symbols (3 copies only) */
    cudaMemcpyToSymbolAsync(c_bW1, bW1, NB*BH*sizeof(float), 0, cudaMemcpyDeviceToDevice, 0);
    cudaMemcpyToSymbolAsync(c_bb1, bb1, BH*sizeof(float),    0, cudaMemcpyDeviceToDevice, 0);

    k_prep_cluster<<<BB/2 + 20, CH>>>(bm, bW2, bWs, bb2, bbs,
                                      eta, cW1, cb1, cW2, cb2, cWs, cbs);

    void* w2t_ptr = nullptr;
    cudaGetSymbolAddress(&w2t_ptr, g_w2t);
    cudaMemcpyToSymbolAsync(c_w2t, w2t_ptr, NB*BH*sizeof(float), 0, cudaMemcpyDeviceToDevice, 0);

    k_node<<<NODES/32, 256>>>(gum, zn, cm, cls, aW1, ab1, aW2, ab2, aWs, absk, atom_out);
    k_edge<<<BB, 256>>>(edge_out);
}

// round 12
// speedup vs baseline: 1.0705x; 1.0705x over previous
#include <cuda_runtime.h>
#include <math.h>

#define BB   1024
#define NN   40
#define ETAD 64
#define KK   32
#define ZDIM 32
#define NA   10
#define NB   5
#define CH   128
#define AH   128
#define BH   64
#define NODES (BB*NN)        /* 40960 */
#define EPB   780            /* C(40,2) edges per batch */
#define ZPAD  36             /* padded row stride (floats), 16B aligned */
#define TMAIN 320            /* k_main threads = 10 warps */

/* ---- dynamic smem layout for k_main (bytes) ---- */
#define SM_ZS    0                      /* zs: 40*36*4        = 5760  */
#define SM_W1    5760                   /* w1s4: 32*32*16     = 16384 */
#define SM_W2T   22144                  /* aw2t: 10*128*4     = 5120  */
#define SM_WST   27264                  /* awst: 10*32*4      = 1280  */
#define SM_AB1   28544                  /* ab1s4: 32*16       = 512   */
#define SM_AB2   29056                  /* ab2s: 16*4         = 64    */
#define SM_UNI   29120                  /* union: max(vs 28800, hsm 20480) */
#define SM_TOTAL (29120 + 28800)        /* 57920 */

/* ---- scratch (static device memory; allocation-free) ---- */
__device__ __align__(16) float g_s[BB*KK];
__device__ __align__(16) float g_wsym[NB*ZDIM*ZDIM];
__device__ __align__(16) float g_w2t[NB*BH];          /* bW2 transposed [t][j] */
__device__ __align__(16) float g_small[40];           /* [0..24]=wss, [28..32]=bb2+bbs */

/* ---- HOT edge-MLP weights: SEPARATE constant symbols (proven LDCU path).
   Packing into one array defeats ptxas uniform-promotion (LDC floor=8 vs
   LDCU floor=1) and doubles the edge loop. Keep split. ---- */
__constant__ __align__(16) float c_bW1[NB*BH];
__constant__ __align__(16) float c_w2t[NB*BH];
__constant__ __align__(16) float c_bb1[BH];

/* ---- f32x2 packed helpers (sm_100+) ---- */
__device__ __forceinline__ unsigned long long pk2(float lo, float hi) {
    unsigned long long r;
    asm("mov.b64 %0, {%1, %2};" : "=l"(r) : "f"(lo), "f"(hi));
    return r;
}
__device__ __forceinline__ void upk2(unsigned long long v, float& lo, float& hi) {
    asm("mov.b64 {%0, %1}, %2;" : "=f"(lo), "=f"(hi) : "l"(v));
}
__device__ __forceinline__ unsigned long long fma2(unsigned long long a,
                                                   unsigned long long b,
                                                   unsigned long long c) {
    unsigned long long r;
    asm("fma.rn.f32x2 %0, %1, %2, %3;" : "=l"(r) : "l"(a), "l"(b), "l"(c));
    return r;
}

/* lex-order edge index for pair (i<j) in a batch of NN nodes */
__device__ __forceinline__ int eidx(int i, int j) {
    return i*(2*NN - 1 - i)/2 + (j - i - 1);
}

/* -------- kernel 0: fused prep + per-batch cluster logits (R10 form) ----- */
__global__ void k_prep_cluster(const float* __restrict__ bm, const float* __restrict__ bW2,
                               const float* __restrict__ bWs, const float* __restrict__ bb2,
                               const float* __restrict__ bbs,
                               const float* __restrict__ eta,
                               const float* __restrict__ cW1, const float* __restrict__ cb1,
                               const float* __restrict__ cW2, const float* __restrict__ cb2,
                               const float* __restrict__ cWs, const float* __restrict__ cbs) {
    int tid = threadIdx.x;
    if (blockIdx.x >= BB) {
        int base = (blockIdx.x - BB) * CH;
        for (int i = base + tid; i < NB*ZDIM*ZDIM; i += 20*CH) {
            int t = i / (ZDIM*ZDIM);
            int r = (i / ZDIM) % ZDIM;
            int c = i % ZDIM;
            g_wsym[i] = 0.5f * (bm[t*ZDIM*ZDIM + r*ZDIM + c] +
                                bm[t*ZDIM*ZDIM + c*ZDIM + r]);
        }
        for (int i = base + tid; i < NB*BH; i += 20*CH) {
            int t = i >> 6, j = i & 63;
            g_w2t[i] = bW2[j*NB + t];
        }
        if (blockIdx.x == BB) {
            if (tid < NB*NB) g_small[tid] = bWs[tid];
            if (tid < NB)    g_small[28 + tid] = bb2[tid] + bbs[tid];
        }
        return;
    }
    __shared__ float eta_sm[ETAD];
    __shared__ float h_sm[CH];
    int b = blockIdx.x;
    if (tid < ETAD) eta_sm[tid] = eta[b*ETAD + tid];
    __syncthreads();
    float acc = cb1[tid];
    #pragma unroll 16
    for (int e = 0; e < ETAD; e++) acc = fmaf(eta_sm[e], cW1[e*CH + tid], acc);
    h_sm[tid] = fmaxf(acc, 0.f);
    __syncthreads();
    if (tid < KK) {
        float s = cb2[tid] + cbs[tid];
        #pragma unroll 16
        for (int j = 0; j < CH; j++) s = fmaf(h_sm[j], cW2[j*KK + tid], s);
        #pragma unroll 16
        for (int e = 0; e < ETAD; e++) s = fmaf(eta_sm[e], cWs[e*KK + tid], s);
        g_s[b*KK + tid] = s;
    }
}

/* -------- kernel 1: FUSED node + edge, block-per-batch, 320 threads ------ */
__global__ __launch_bounds__(TMAIN)
void k_main(const float* __restrict__ gum, const float* __restrict__ zn,
            const float* __restrict__ cm,  const float* __restrict__ cls,
            const float* __restrict__ aW1, const float* __restrict__ ab1,
            const float* __restrict__ aW2, const float* __restrict__ ab2,
            const float* __restrict__ aWs, const float* __restrict__ absk,
            float* __restrict__ atom_out, float* __restrict__ edge_out) {
    extern __shared__ __align__(16) char smraw[];
    float*  zs    = (float*) (smraw + SM_ZS);    /* z[j][d], ZPAD stride */
    float4* w1s4  = (float4*)(smraw + SM_W1);
    float*  aw2t  = (float*) (smraw + SM_W2T);
    float*  awst  = (float*) (smraw + SM_WST);
    float4* ab1s4 = (float4*)(smraw + SM_AB1);
    float*  ab2s  = (float*) (smraw + SM_AB2);
    float*  uni   = (float*) (smraw + SM_UNI);   /* hsm (node phase) / vs (edge phase) */

    int tid  = threadIdx.x;
    int warp = tid >> 5;
    int lane = tid & 31;
    int b    = blockIdx.x;
    int nodeb = b*NN;

    /* ---- stage atom weights ---- */
    for (int i = tid; i < ZDIM*32; i += TMAIN) w1s4[i] = ((const float4*)aW1)[i];
    for (int i = tid; i < NA*AH;  i += TMAIN) { int o = i / AH, j = i % AH; aw2t[i] = aW2[j*NA + o]; }
    for (int i = tid; i < NA*ZDIM; i += TMAIN) { int o = i / ZDIM, d = i % ZDIM; awst[i] = aWs[d*NA + o]; }
    if (tid < 32) ab1s4[tid] = ((const float4*)ab1)[tid];
    if (tid < NA) ab2s[tid]  = ab2[tid] + absk[tid];
    __syncthreads();

    /* ---- node phase 1: argmax + z (4 nodes per warp, rows 4w..4w+3) ---- */
    float srow = g_s[b*KK + lane];
    #pragma unroll
    for (int u = 0; u < 4; u++) {
        int nloc = warp*4 + u;
        int node = nodeb + nloc;
        float val = srow + gum[node*KK + lane];
        int idx = lane;
        #pragma unroll
        for (int off = 16; off; off >>= 1) {
            float ov = __shfl_xor_sync(0xffffffffu, val, off);
            int   oi = __shfl_xor_sync(0xffffffffu, idx, off);
            if (ov > val || (ov == val && oi < idx)) { val = ov; idx = oi; }
        }
        int kmax = idx;
        float ls = cls[kmax*ZDIM + lane];
        float sg = __expf(fminf(fmaxf(ls, -20.f), 30.f));
        float z  = fmaf(zn[node*ZDIM + lane], sg, cm[kmax*ZDIM + lane]);
        zs[nloc*ZPAD + lane] = z;
    }
    __syncwarp();

    /* ---- node phase 2: hidden layer (one weight load serves 4 nodes) ---- */
    {
        float4 acc0 = ab1s4[lane], acc1 = acc0, acc2 = acc0, acc3 = acc0;
        #pragma unroll
        for (int d = 0; d < ZDIM; d++) {
            float4 w = w1s4[d*32 + lane];
            float z0 = zs[(warp*4 + 0)*ZPAD + d];
            float z1 = zs[(warp*4 + 1)*ZPAD + d];
            float z2 = zs[(warp*4 + 2)*ZPAD + d];
            float z3 = zs[(warp*4 + 3)*ZPAD + d];
            acc0.x = fmaf(z0, w.x, acc0.x); acc0.y = fmaf(z0, w.y, acc0.y);
            acc0.z = fmaf(z0, w.z, acc0.z); acc0.w = fmaf(z0, w.w, acc0.w);
            acc1.x = fmaf(z1, w.x, acc1.x); acc1.y = fmaf(z1, w.y, acc1.y);
            acc1.z = fmaf(z1, w.z, acc1.z); acc1.w = fmaf(z1, w.w, acc1.w);
            acc2.x = fmaf(z2, w.x, acc2.x); acc2.y = fmaf(z2, w.y, acc2.y);
            acc2.z = fmaf(z2, w.z, acc2.z); acc2.w = fmaf(z2, w.w, acc2.w);
            acc3.x = fmaf(z3, w.x, acc3.x); acc3.y = fmaf(z3, w.y, acc3.y);
            acc3.z = fmaf(z3, w.z, acc3.z); acc3.w = fmaf(z3, w.w, acc3.w);
        }
        #define RELU4(a) { a.x=fmaxf(a.x,0.f); a.y=fmaxf(a.y,0.f); a.z=fmaxf(a.z,0.f); a.w=fmaxf(a.w,0.f); }
        RELU4(acc0) RELU4(acc1) RELU4(acc2) RELU4(acc3)
        reinterpret_cast<float4*>(uni + (warp*4 + 0)*AH)[lane] = acc0;
        reinterpret_cast<float4*>(uni + (warp*4 + 1)*AH)[lane] = acc1;
        reinterpret_cast<float4*>(uni + (warp*4 + 2)*AH)[lane] = acc2;
        reinterpret_cast<float4*>(uni + (warp*4 + 3)*AH)[lane] = acc3;
    }
    __syncwarp();

    /* ---- node phase 3: output layer (40 (node,out) pairs per warp) ---- */
    #pragma unroll
    for (int pass = 0; pass < 2; pass++) {
        int q = pass*32 + lane;
        if (q < 40) {
            int u = q / 10, o = q % 10;
            int nloc = warp*4 + u;
            float s = ab2s[o];
            const float* hrow = uni + nloc*AH;
            #pragma unroll 8
            for (int j4 = 0; j4 < AH/4; j4++) {
                float4 h = *reinterpret_cast<const float4*>(&hrow[j4*4]);
                float4 w = *reinterpret_cast<const float4*>(&aw2t[o*AH + j4*4]);
                s = fmaf(h.x, w.x, fmaf(h.y, w.y, fmaf(h.z, w.z, fmaf(h.w, w.w, s))));
            }
            #pragma unroll
            for (int d4 = 0; d4 < ZDIM/4; d4++) {
                float4 zv = *reinterpret_cast<const float4*>(&zs[nloc*ZPAD + d4*4]);
                float4 w  = *reinterpret_cast<const float4*>(&awst[o*ZDIM + d4*4]);
                s = fmaf(zv.x, w.x, fmaf(zv.y, w.y, fmaf(zv.z, w.z, fmaf(zv.w, w.w, s))));
            }
            atom_out[(nodeb + nloc)*NA + o] = s;
        }
    }
    __syncthreads();   /* all z in zs; all hsm reads done -> vs may overwrite uni */

    /* ---- edge phase: v[t][j][d] = sum_c Wsym[t][c][d] * z[j][c] ----
       NN*8 = 320 items == blockDim: exactly one per thread            */
    {
        float* vs = uni;
        int j = tid >> 3, d4 = tid & 7;
        #pragma unroll
        for (int t = 0; t < NB; t++) {
            float4 acc = make_float4(0.f, 0.f, 0.f, 0.f);
            const float4* W = reinterpret_cast<const float4*>(g_wsym) + t*256 + d4;
            #pragma unroll 8
            for (int c = 0; c < ZDIM; c++) {
                float zc = zs[j*ZPAD + c];
                float4 w = W[c*8];
                acc.x = fmaf(zc, w.x, acc.x);
                acc.y = fmaf(zc, w.y, acc.y);
                acc.z = fmaf(zc, w.z, acc.z);
                acc.w = fmaf(zc, w.w, acc.w);
            }
            *reinterpret_cast<float4*>(&vs[t*NN*ZPAD + j*ZPAD + d4*4]) = acc;
        }
    }
    __syncthreads();

    float* vs   = uni;
    float* outb = edge_out + (size_t)b * EPB * NB;

    for (int w = tid; w < 400; w += TMAIN) {
        int i0, i1, j;
        if (w < 380) {
            int I = (int)(19.5f - sqrtf(380.25f - (float)w));
            if (I > 18) I = 18;
            if (I < 0)  I = 0;
            int c = I*(39 - I);
            if (w < c)  { I--; c = I*(39 - I); }
            else        { int c2 = (I + 1)*(38 - I); if (w >= c2) { I++; c = c2; } }
            j  = 2*I + 2 + (w - c);
            i0 = 2*I; i1 = 2*I + 1;
        } else {
            int I = w - 380;
            i0 = 2*I; i1 = 2*I; j = 2*I + 1;
        }
        int e0 = eidx(i0, j), e1 = eidx(i1, j);

        /* bilinear: v row shared across both edges */
        float bil0[NB], bil1[NB];
        #pragma unroll
        for (int t = 0; t < NB; t++) { bil0[t] = 0.f; bil1[t] = 0.f; }
        #pragma unroll
        for (int d4 = 0; d4 < 8; d4++) {
            float4 z0 = *reinterpret_cast<const float4*>(&zs[i0*ZPAD + d4*4]);
            float4 z1 = *reinterpret_cast<const float4*>(&zs[i1*ZPAD + d4*4]);
            #pragma unroll
            for (int t = 0; t < NB; t++) {
                float4 v = *reinterpret_cast<const float4*>(&vs[t*NN*ZPAD + j*ZPAD + d4*4]);
                bil0[t] = fmaf(z0.w, v.w, fmaf(z0.z, v.z, fmaf(z0.y, v.y, fmaf(z0.x, v.x, bil0[t]))));
                bil1[t] = fmaf(z1.w, v.w, fmaf(z1.z, v.z, fmaf(z1.y, v.y, fmaf(z1.x, v.x, bil1[t]))));
            }
        }

        /* skip path (cold weights via uniform global loads) + pack */
        unsigned long long oo0[NB], oo1[NB], bp0[NB], bp1[NB];
        #pragma unroll
        for (int t = 0; t < NB; t++) {
            float base = __ldg(&g_small[28 + t]);
            float s0 = base, s1 = base;
            #pragma unroll
            for (int u = 0; u < NB; u++) {
                float wv = __ldg(&g_small[u*NB + t]);
                s0 = fmaf(bil0[u], wv, s0);
                s1 = fmaf(bil1[u], wv, s1);
            }
            oo0[t] = pk2(s0, 0.f);
            oo1[t] = pk2(s1, 0.f);
            bp0[t] = pk2(bil0[t], bil0[t]);
            bp1[t] = pk2(bil1[t], bil1[t]);
        }

        /* MLP: hidden pairs, weights via uniform constant (LDCU) loads */
        #pragma unroll 4
        for (int jp = 0; jp < BH/2; jp++) {
            unsigned long long b1p =
                *reinterpret_cast<const unsigned long long*>(&c_bb1[2*jp]);
            unsigned long long h0 = b1p, h1 = b1p;
            #pragma unroll
            for (int t = 0; t < NB; t++) {
                unsigned long long w1p =
                    *reinterpret_cast<const unsigned long long*>(&c_bW1[t*BH + 2*jp]);
                h0 = fma2(bp0[t], w1p, h0);
                h1 = fma2(bp1[t], w1p, h1);
            }
            { float x, y; upk2(h0, x, y); h0 = pk2(fmaxf(x, 0.f), fmaxf(y, 0.f)); }
            { float x, y; upk2(h1, x, y); h1 = pk2(fmaxf(x, 0.f), fmaxf(y, 0.f)); }
            #pragma unroll
            for (int t = 0; t < NB; t++) {
                unsigned long long w2p =
                    *reinterpret_cast<const unsigned long long*>(&c_w2t[t*BH + 2*jp]);
                oo0[t] = fma2(h0, w2p, oo0[t]);
                oo1[t] = fma2(h1, w2p, oo1[t]);
            }
        }

        /* reduce halves, softmax, store */
        {
            float o[NB];
            #pragma unroll
            for (int t = 0; t < NB; t++) { float x, y; upk2(oo0[t], x, y); o[t] = x + y; }
            float m = o[0];
            #pragma unroll
            for (int t = 1; t < NB; t++) m = fmaxf(m, o[t]);
            float s = 0.f, ex[NB];
            #pragma unroll
            for (int t = 0; t < NB; t++) { ex[t] = __expf(o[t] - m); s += ex[t]; }
            float inv = __fdividef(1.f, s);
            #pragma unroll
            for (int t = 0; t < NB; t++) outb[e0*NB + t] = ex[t] * inv;
        }
        {
            float o[NB];
            #pragma unroll
            for (int t = 0; t < NB; t++) { float x, y; upk2(oo1[t], x, y); o[t] = x + y; }
            float m = o[0];
            #pragma unroll
            for (int t = 1; t < NB; t++) m = fmaxf(m, o[t]);
            float s = 0.f, ex[NB];
            #pragma unroll
            for (int t = 0; t < NB; t++) { ex[t] = __expf(o[t] - m); s += ex[t]; }
            float inv = __fdividef(1.f, s);
            #pragma unroll
            for (int t = 0; t < NB; t++) outb[e1*NB + t] = ex[t] * inv;
        }
    }
}

/* ------------------------- launch ------------------------- */
extern "C" void kernel_launch(void* const* d_in, const int* in_sizes, int n_in,
                              void* d_out, int out_size) {
    const float* eta  = (const float*)d_in[0];
    const float* gum  = (const float*)d_in[1];
    const float* zn   = (const float*)d_in[2];
    const float* cW1  = (const float*)d_in[3];
    const float* cb1  = (const float*)d_in[4];
    const float* cW2  = (const float*)d_in[5];
    const float* cb2  = (const float*)d_in[6];
    const float* cWs  = (const float*)d_in[7];
    const float* cbs  = (const float*)d_in[8];
    const float* cm   = (const float*)d_in[9];
    const float* cls  = (const float*)d_in[10];
    const float* aW1  = (const float*)d_in[11];
    const float* ab1  = (const float*)d_in[12];
    const float* aW2  = (const float*)d_in[13];
    const float* ab2  = (const float*)d_in[14];
    const float* aWs  = (const float*)d_in[15];
    const float* absk = (const float*)d_in[16];
    const float* bm   = (const float*)d_in[17];
    const float* bW1  = (const float*)d_in[18];
    const float* bb1  = (const float*)d_in[19];
    const float* bW2  = (const float*)d_in[20];
    const float* bb2  = (const float*)d_in[21];
    const float* bWs  = (const float*)d_in[22];
    const float* bbs  = (const float*)d_in[23];

    float* atom_out = (float*)d_out;
    float* edge_out = atom_out + (size_t)NODES * NA;

    /* opt-in to >48KB dynamic smem for k_main (host-side attr, idempotent) */
    cudaFuncSetAttribute(k_main, cudaFuncAttributeMaxDynamicSharedMemorySize, SM_TOTAL);

    /* hot edge-MLP weights -> separate constant symbols */
    cudaMemcpyToSymbolAsync(c_bW1, bW1, NB*BH*sizeof(float), 0, cudaMemcpyDeviceToDevice, 0);
    cudaMemcpyToSymbolAsync(c_bb1, bb1, BH*sizeof(float),    0, cudaMemcpyDeviceToDevice, 0);

    k_prep_cluster<<<BB + 20, CH>>>(bm, bW2, bWs, bb2, bbs,
                                    eta, cW1, cb1, cW2, cb2, cWs, cbs);

    void* w2t_ptr = nullptr;
    cudaGetSymbolAddress(&w2t_ptr, g_w2t);
    cudaMemcpyToSymbolAsync(c_w2t, w2t_ptr, NB*BH*sizeof(float), 0, cudaMemcpyDeviceToDevice, 0);

    k_main<<<BB, TMAIN, SM_TOTAL>>>(gum, zn, cm, cls, aW1, ab1, aW2, ab2, aWs, absk,
                                    atom_out, edge_out);
}

// round 13
// speedup vs baseline: 1.4935x; 1.3951x over previous
#include <cuda_runtime.h>
#include <math.h>

#define BB   1024
#define NN   40
#define ETAD 64
#define KK   32
#define ZDIM 32
#define NA   10
#define NB   5
#define CH   128
#define AH   128
#define BH   64
#define NODES (BB*NN)        /* 40960 */
#define EPB   780            /* C(40,2) edges per batch */
#define ZPAD  36             /* z / v / awst padded row stride (floats) */
#define HPADR 132            /* hsm / aw2t padded row stride (floats): bank-conflict-free-ish */
#define TMAIN 320            /* k_main threads = 10 warps */

/* ---- dynamic smem layout for k_main (bytes) ---- */
#define SM_ZS    0                      /* zs: 40*36*4        = 5760  */
#define SM_W1    5760                   /* w1s4: 32*32*16     = 16384 */
#define SM_W2T   22144                  /* aw2t: 10*132*4     = 5280  */
#define SM_WST   27424                  /* awst: 10*36*4      = 1440  */
#define SM_AB1   28864                  /* ab1s4: 32*16       = 512   */
#define SM_AB2   29376                  /* ab2s               = 64    */
#define SM_UNI   29440                  /* union: max(vs 28800, hsm 40*132*4=21120) */
#define SM_TOTAL (29440 + 28800)        /* 58240 */

/* ---- scratch (static device memory; allocation-free) ---- */
__device__ __align__(16) float g_s[BB*KK];
__device__ __align__(16) float g_wsym[NB*ZDIM*ZDIM];
__device__ __align__(16) float g_w2t[NB*BH];          /* bW2 transposed [t][j] */
__device__ __align__(16) float g_small[40];           /* [0..24]=wss, [28..32]=bb2+bbs */

/* ---- HOT edge-MLP weights: SEPARATE constant symbols (proven LDCU path).
   Packing into one array defeats ptxas uniform-promotion (LDC floor=8 vs
   LDCU floor=1) and doubles the edge loop. Keep split. ---- */
__constant__ __align__(16) float c_bW1[NB*BH];
__constant__ __align__(16) float c_w2t[NB*BH];
__constant__ __align__(16) float c_bb1[BH];

/* ---- f32x2 packed helpers (sm_100+) ---- */
__device__ __forceinline__ unsigned long long pk2(float lo, float hi) {
    unsigned long long r;
    asm("mov.b64 %0, {%1, %2};" : "=l"(r) : "f"(lo), "f"(hi));
    return r;
}
__device__ __forceinline__ void upk2(unsigned long long v, float& lo, float& hi) {
    asm("mov.b64 {%0, %1}, %2;" : "=f"(lo), "=f"(hi) : "l"(v));
}
__device__ __forceinline__ unsigned long long fma2(unsigned long long a,
                                                   unsigned long long b,
                                                   unsigned long long c) {
    unsigned long long r;
    asm("fma.rn.f32x2 %0, %1, %2, %3;" : "=l"(r) : "l"(a), "l"(b), "l"(c));
    return r;
}

/* lex-order edge index for pair (i<j) in a batch of NN nodes */
__device__ __forceinline__ int eidx(int i, int j) {
    return i*(2*NN - 1 - i)/2 + (j - i - 1);
}

/* -------- kernel 0: fused prep + per-batch cluster logits -------- */
__global__ void k_prep_cluster(const float* __restrict__ bm, const float* __restrict__ bW2,
                               const float* __restrict__ bWs, const float* __restrict__ bb2,
                               const float* __restrict__ bbs,
                               const float* __restrict__ eta,
                               const float* __restrict__ cW1, const float* __restrict__ cb1,
                               const float* __restrict__ cW2, const float* __restrict__ cb2,
                               const float* __restrict__ cWs, const float* __restrict__ cbs) {
    int tid = threadIdx.x;
    if (blockIdx.x >= BB) {
        int base = (blockIdx.x - BB) * CH;
        for (int i = base + tid; i < NB*ZDIM*ZDIM; i += 20*CH) {
            int t = i / (ZDIM*ZDIM);
            int r = (i / ZDIM) % ZDIM;
            int c = i % ZDIM;
            g_wsym[i] = 0.5f * (bm[t*ZDIM*ZDIM + r*ZDIM + c] +
                                bm[t*ZDIM*ZDIM + c*ZDIM + r]);
        }
        for (int i = base + tid; i < NB*BH; i += 20*CH) {
            int t = i >> 6, j = i & 63;
            g_w2t[i] = bW2[j*NB + t];
        }
        if (blockIdx.x == BB) {
            if (tid < NB*NB) g_small[tid] = bWs[tid];
            if (tid < NB)    g_small[28 + tid] = bb2[tid] + bbs[tid];
        }
        return;
    }
    __shared__ float eta_sm[ETAD];
    __shared__ float h_sm[CH];
    int b = blockIdx.x;
    if (tid < ETAD) eta_sm[tid] = eta[b*ETAD + tid];
    __syncthreads();
    float acc = cb1[tid];
    #pragma unroll 16
    for (int e = 0; e < ETAD; e++) acc = fmaf(eta_sm[e], cW1[e*CH + tid], acc);
    h_sm[tid] = fmaxf(acc, 0.f);
    __syncthreads();
    if (tid < KK) {
        float s = cb2[tid] + cbs[tid];
        #pragma unroll 16
        for (int j = 0; j < CH; j++) s = fmaf(h_sm[j], cW2[j*KK + tid], s);
        #pragma unroll 16
        for (int e = 0; e < ETAD; e++) s = fmaf(eta_sm[e], cWs[e*KK + tid], s);
        g_s[b*KK + tid] = s;
    }
}

/* -------- kernel 1: FUSED node + edge, block-per-batch, 320 threads ------ */
__global__ __launch_bounds__(TMAIN)
void k_main(const float* __restrict__ gum, const float* __restrict__ zn,
            const float* __restrict__ cm,  const float* __restrict__ cls,
            const float* __restrict__ aW1, const float* __restrict__ ab1,
            const float* __restrict__ aW2, const float* __restrict__ ab2,
            const float* __restrict__ aWs, const float* __restrict__ absk,
            float* __restrict__ atom_out, float* __restrict__ edge_out) {
    extern __shared__ __align__(16) char smraw[];
    float*  __restrict__ zs    = (float*) (smraw + SM_ZS);    /* z[j][d], ZPAD stride */
    float4* __restrict__ w1s4  = (float4*)(smraw + SM_W1);
    float*  __restrict__ aw2t  = (float*) (smraw + SM_W2T);   /* [o][j], HPADR stride */
    float*  __restrict__ awst  = (float*) (smraw + SM_WST);   /* [o][d], ZPAD stride  */
    float4* __restrict__ ab1s4 = (float4*)(smraw + SM_AB1);
    float*  __restrict__ ab2s  = (float*) (smraw + SM_AB2);
    float*  __restrict__ uni   = (float*) (smraw + SM_UNI);   /* hsm (HPADR) / vs */

    int tid  = threadIdx.x;
    int warp = tid >> 5;
    int lane = tid & 31;
    int b    = blockIdx.x;
    int nodeb = b*NN;

    /* ---- stage atom weights (padded rows) ---- */
    for (int i = tid; i < ZDIM*32; i += TMAIN) w1s4[i] = ((const float4*)aW1)[i];
    for (int i = tid; i < NA*AH;  i += TMAIN) { int o = i / AH, j = i % AH; aw2t[o*HPADR + j] = aW2[j*NA + o]; }
    for (int i = tid; i < NA*ZDIM; i += TMAIN) { int o = i / ZDIM, d = i % ZDIM; awst[o*ZPAD + d] = aWs[d*NA + o]; }
    if (tid < 32) ab1s4[tid] = ((const float4*)ab1)[tid];
    if (tid < NA) ab2s[tid]  = ab2[tid] + absk[tid];
    __syncthreads();

    /* ---- node phase 1: argmax + z (4 nodes per warp, rows 4w..4w+3) ---- */
    float srow = g_s[b*KK + lane];
    #pragma unroll
    for (int u = 0; u < 4; u++) {
        int nloc = warp*4 + u;
        int node = nodeb + nloc;
        float val = srow + gum[node*KK + lane];
        int idx = lane;
        #pragma unroll
        for (int off = 16; off; off >>= 1) {
            float ov = __shfl_xor_sync(0xffffffffu, val, off);
            int   oi = __shfl_xor_sync(0xffffffffu, idx, off);
            if (ov > val || (ov == val && oi < idx)) { val = ov; idx = oi; }
        }
        int kmax = idx;
        float ls = cls[kmax*ZDIM + lane];
        float sg = __expf(fminf(fmaxf(ls, -20.f), 30.f));
        float z  = fmaf(zn[node*ZDIM + lane], sg, cm[kmax*ZDIM + lane]);
        zs[nloc*ZPAD + lane] = z;
    }
    __syncwarp();

    /* ---- node phase 2: hidden layer (one weight load serves 4 nodes) ---- */
    {
        float4 acc0 = ab1s4[lane], acc1 = acc0, acc2 = acc0, acc3 = acc0;
        #pragma unroll
        for (int d = 0; d < ZDIM; d++) {
            float4 w = w1s4[d*32 + lane];
            float z0 = zs[(warp*4 + 0)*ZPAD + d];
            float z1 = zs[(warp*4 + 1)*ZPAD + d];
            float z2 = zs[(warp*4 + 2)*ZPAD + d];
            float z3 = zs[(warp*4 + 3)*ZPAD + d];
            acc0.x = fmaf(z0, w.x, acc0.x); acc0.y = fmaf(z0, w.y, acc0.y);
            acc0.z = fmaf(z0, w.z, acc0.z); acc0.w = fmaf(z0, w.w, acc0.w);
            acc1.x = fmaf(z1, w.x, acc1.x); acc1.y = fmaf(z1, w.y, acc1.y);
            acc1.z = fmaf(z1, w.z, acc1.z); acc1.w = fmaf(z1, w.w, acc1.w);
            acc2.x = fmaf(z2, w.x, acc2.x); acc2.y = fmaf(z2, w.y, acc2.y);
            acc2.z = fmaf(z2, w.z, acc2.z); acc2.w = fmaf(z2, w.w, acc2.w);
            acc3.x = fmaf(z3, w.x, acc3.x); acc3.y = fmaf(z3, w.y, acc3.y);
            acc3.z = fmaf(z3, w.z, acc3.z); acc3.w = fmaf(z3, w.w, acc3.w);
        }
        #define RELU4(a) { a.x=fmaxf(a.x,0.f); a.y=fmaxf(a.y,0.f); a.z=fmaxf(a.z,0.f); a.w=fmaxf(a.w,0.f); }
        RELU4(acc0) RELU4(acc1) RELU4(acc2) RELU4(acc3)
        /* hsm rows at HPADR stride: base nloc*528B, 16B-aligned (528 = 33*16) */
        reinterpret_cast<float4*>(uni + (warp*4 + 0)*HPADR)[lane] = acc0;
        reinterpret_cast<float4*>(uni + (warp*4 + 1)*HPADR)[lane] = acc1;
        reinterpret_cast<float4*>(uni + (warp*4 + 2)*HPADR)[lane] = acc2;
        reinterpret_cast<float4*>(uni + (warp*4 + 3)*HPADR)[lane] = acc3;
    }
    __syncwarp();

    /* ---- node phase 3: output layer (40 (node,out) pairs per warp) ---- */
    #pragma unroll
    for (int pass = 0; pass < 2; pass++) {
        int q = pass*32 + lane;
        if (q < 40) {
            int u = q / 10, o = q % 10;
            int nloc = warp*4 + u;
            float s = ab2s[o];
            const float* __restrict__ hrow = uni + nloc*HPADR;
            const float* __restrict__ wrow = aw2t + o*HPADR;
            #pragma unroll 8
            for (int j4 = 0; j4 < AH/4; j4++) {
                float4 h = *reinterpret_cast<const float4*>(&hrow[j4*4]);
                float4 w = *reinterpret_cast<const float4*>(&wrow[j4*4]);
                s = fmaf(h.x, w.x, fmaf(h.y, w.y, fmaf(h.z, w.z, fmaf(h.w, w.w, s))));
            }
            const float* __restrict__ wsrow = awst + o*ZPAD;
            #pragma unroll
            for (int d4 = 0; d4 < ZDIM/4; d4++) {
                float4 zv = *reinterpret_cast<const float4*>(&zs[nloc*ZPAD + d4*4]);
                float4 w  = *reinterpret_cast<const float4*>(&wsrow[d4*4]);
                s = fmaf(zv.x, w.x, fmaf(zv.y, w.y, fmaf(zv.z, w.z, fmaf(zv.w, w.w, s))));
            }
            atom_out[(nodeb + nloc)*NA + o] = s;
        }
    }
    __syncthreads();   /* all z in zs; all hsm reads done -> vs may overwrite uni */

    /* ---- edge phase: v[t][j][d] = sum_c Wsym[t][c][d] * z[j][c] ----
       NN*8 = 320 items == blockDim: exactly one per thread            */
    {
        float* __restrict__ vsw = uni;
        int j = tid >> 3, d4 = tid & 7;
        #pragma unroll
        for (int t = 0; t < NB; t++) {
            float4 acc = make_float4(0.f, 0.f, 0.f, 0.f);
            const float4* __restrict__ W = reinterpret_cast<const float4*>(g_wsym) + t*256 + d4;
            #pragma unroll 8
            for (int c = 0; c < ZDIM; c++) {
                float zc = zs[j*ZPAD + c];
                float4 w = W[c*8];
                acc.x = fmaf(zc, w.x, acc.x);
                acc.y = fmaf(zc, w.y, acc.y);
                acc.z = fmaf(zc, w.z, acc.z);
                acc.w = fmaf(zc, w.w, acc.w);
            }
            *reinterpret_cast<float4*>(&vsw[t*NN*ZPAD + j*ZPAD + d4*4]) = acc;
        }
    }
    __syncthreads();

    const float* __restrict__ vs = uni;
    float* __restrict__ outb = edge_out + (size_t)b * EPB * NB;

    for (int w = tid; w < 400; w += TMAIN) {
        int i0, i1, j;
        if (w < 380) {
            int I = (int)(19.5f - sqrtf(380.25f - (float)w));
            if (I > 18) I = 18;
            if (I < 0)  I = 0;
            int c = I*(39 - I);
            if (w < c)  { I--; c = I*(39 - I); }
            else        { int c2 = (I + 1)*(38 - I); if (w >= c2) { I++; c = c2; } }
            j  = 2*I + 2 + (w - c);
            i0 = 2*I; i1 = 2*I + 1;
        } else {
            int I = w - 380;
            i0 = 2*I; i1 = 2*I; j = 2*I + 1;
        }
        int e0 = eidx(i0, j), e1 = eidx(i1, j);

        /* bilinear: v row shared across both edges */
        float bil0[NB], bil1[NB];
        #pragma unroll
        for (int t = 0; t < NB; t++) { bil0[t] = 0.f; bil1[t] = 0.f; }
        #pragma unroll
        for (int d4 = 0; d4 < 8; d4++) {
            float4 z0 = *reinterpret_cast<const float4*>(&zs[i0*ZPAD + d4*4]);
            float4 z1 = *reinterpret_cast<const float4*>(&zs[i1*ZPAD + d4*4]);
            #pragma unroll
            for (int t = 0; t < NB; t++) {
                float4 v = *reinterpret_cast<const float4*>(&vs[t*NN*ZPAD + j*ZPAD + d4*4]);
                bil0[t] = fmaf(z0.w, v.w, fmaf(z0.z, v.z, fmaf(z0.y, v.y, fmaf(z0.x, v.x, bil0[t]))));
                bil1[t] = fmaf(z1.w, v.w, fmaf(z1.z, v.z, fmaf(z1.y, v.y, fmaf(z1.x, v.x, bil1[t]))));
            }
        }

        /* skip path (cold weights via uniform global loads) + pack */
        unsigned long long oo0[NB], oo1[NB], bp0[NB], bp1[NB];
        #pragma unroll
        for (int t = 0; t < NB; t++) {
            float base = __ldg(&g_small[28 + t]);
            float s0 = base, s1 = base;
            #pragma unroll
            for (int u = 0; u < NB; u++) {
                float wv = __ldg(&g_small[u*NB + t]);
                s0 = fmaf(bil0[u], wv, s0);
                s1 = fmaf(bil1[u], wv, s1);
            }
            oo0[t] = pk2(s0, 0.f);
            oo1[t] = pk2(s1, 0.f);
            bp0[t] = pk2(bil0[t], bil0[t]);
            bp1[t] = pk2(bil1[t], bil1[t]);
        }

        /* MLP: hidden pairs, weights via uniform constant (LDCU) loads */
        #pragma unroll 4
        for (int jp = 0; jp < BH/2; jp++) {
            unsigned long long b1p =
                *reinterpret_cast<const unsigned long long*>(&c_bb1[2*jp]);
            unsigned long long h0 = b1p, h1 = b1p;
            #pragma unroll
            for (int t = 0; t < NB; t++) {
                unsigned long long w1p =
                    *reinterpret_cast<const unsigned long long*>(&c_bW1[t*BH + 2*jp]);
                h0 = fma2(bp0[t], w1p, h0);
                h1 = fma2(bp1[t], w1p, h1);
            }
            { float x, y; upk2(h0, x, y); h0 = pk2(fmaxf(x, 0.f), fmaxf(y, 0.f)); }
            { float x, y; upk2(h1, x, y); h1 = pk2(fmaxf(x, 0.f), fmaxf(y, 0.f)); }
            #pragma unroll
            for (int t = 0; t < NB; t++) {
                unsigned long long w2p =
                    *reinterpret_cast<const unsigned long long*>(&c_w2t[t*BH + 2*jp]);
                oo0[t] = fma2(h0, w2p, oo0[t]);
                oo1[t] = fma2(h1, w2p, oo1[t]);
            }
        }

        /* reduce halves, softmax, store */
        {
            float o[NB];
            #pragma unroll
            for (int t = 0; t < NB; t++) { float x, y; upk2(oo0[t], x, y); o[t] = x + y; }
            float m = o[0];
            #pragma unroll
            for (int t = 1; t < NB; t++) m = fmaxf(m, o[t]);
            float s = 0.f, ex[NB];
            #pragma unroll
            for (int t = 0; t < NB; t++) { ex[t] = __expf(o[t] - m); s += ex[t]; }
            float inv = __fdividef(1.f, s);
            #pragma unroll
            for (int t = 0; t < NB; t++) outb[e0*NB + t] = ex[t] * inv;
        }
        {
            float o[NB];
            #pragma unroll
            for (int t = 0; t < NB; t++) { float x, y; upk2(oo1[t], x, y); o[t] = x + y; }
            float m = o[0];
            #pragma unroll
            for (int t = 1; t < NB; t++) m = fmaxf(m, o[t]);
            float s = 0.f, ex[NB];
            #pragma unroll
            for (int t = 0; t < NB; t++) { ex[t] = __expf(o[t] - m); s += ex[t]; }
            float inv = __fdividef(1.f, s);
            #pragma unroll
            for (int t = 0; t < NB; t++) outb[e1*NB + t] = ex[t] * inv;
        }
    }
}

/* ------------------------- launch ------------------------- */
extern "C" void kernel_launch(void* const* d_in, const int* in_sizes, int n_in,
                              void* d_out, int out_size) {
    const float* eta  = (const float*)d_in[0];
    const float* gum  = (const float*)d_in[1];
    const float* zn   = (const float*)d_in[2];
    const float* cW1  = (const float*)d_in[3];
    const float* cb1  = (const float*)d_in[4];
    const float* cW2  = (const float*)d_in[5];
    const float* cb2  = (const float*)d_in[6];
    const float* cWs  = (const float*)d_in[7];
    const float* cbs  = (const float*)d_in[8];
    const float* cm   = (const float*)d_in[9];
    const float* cls  = (const float*)d_in[10];
    const float* aW1  = (const float*)d_in[11];
    const float* ab1  = (const float*)d_in[12];
    const float* aW2  = (const float*)d_in[13];
    const float* ab2  = (const float*)d_in[14];
    const float* aWs  = (const float*)d_in[15];
    const float* absk = (const float*)d_in[16];
    const float* bm   = (const float*)d_in[17];
    const float* bW1  = (const float*)d_in[18];
    const float* bb1  = (const float*)d_in[19];
    const float* bW2  = (const float*)d_in[20];
    const float* bb2  = (const float*)d_in[21];
    const float* bWs  = (const float*)d_in[22];
    const float* bbs  = (const float*)d_in[23];

    float* atom_out = (float*)d_out;
    float* edge_out = atom_out + (size_t)NODES * NA;

    cudaFuncSetAttribute(k_main, cudaFuncAttributeMaxDynamicSharedMemorySize, SM_TOTAL);

    /* hot edge-MLP weights -> separate constant symbols */
    cudaMemcpyToSymbolAsync(c_bW1, bW1, NB*BH*sizeof(float), 0, cudaMemcpyDeviceToDevice, 0);
    cudaMemcpyToSymbolAsync(c_bb1, bb1, BH*sizeof(float),    0, cudaMemcpyDeviceToDevice, 0);

    k_prep_cluster<<<BB + 20, CH>>>(bm, bW2, bWs, bb2, bbs,
                                    eta, cW1, cb1, cW2, cb2, cWs, cbs);

    void* w2t_ptr = nullptr;
    cudaGetSymbolAddress(&w2t_ptr, g_w2t);
    cudaMemcpyToSymbolAsync(c_w2t, w2t_ptr, NB*BH*sizeof(float), 0, cudaMemcpyDeviceToDevice, 0);

    k_main<<<BB, TMAIN, SM_TOTAL>>>(gum, zn, cm, cls, aW1, ab1, aW2, ab2, aWs, absk,
                                    atom_out, edge_out);
}

// round 14
// speedup vs baseline: 1.5725x; 1.0529x over previous
#include <cuda_runtime.h>
#include <math.h>

#define BB   1024
#define NN   40
#define ETAD 64
#define KK   32
#define ZDIM 32
#define NA   10
#define NB   5
#define CH   128
#define AH   128
#define BH   64
#define NODES (BB*NN)        /* 40960 */
#define EPB   780            /* C(40,2) edges per batch */
#define ZPAD  36             /* z / v / awst padded row stride (floats) */
#define HPADR 132            /* hsm / aw2t padded row stride (floats) */
#define TMAIN 320            /* k_main threads = 10 warps */

/* ---- dynamic smem layout for k_main (bytes) ---- */
#define SM_ZS    0                      /* zs: 40*36*4        = 5760  */
#define SM_W1    5760                   /* w1s4: 16384; after node phase reused for wsymS (20480 <= 21664) */
#define SM_W2T   22144                  /* aw2t: 10*132*4     = 5280  */
#define SM_WST   27424                  /* awst: 10*36*4      = 1440  */
#define SM_AB1   28864                  /* ab1s4: 32*16       = 512   */
#define SM_AB2   29376                  /* ab2s               = 64    */
#define SM_UNI   29440                  /* union: max(vs 28800, hsm 40*132*4=21120) */
#define SM_TOTAL (29440 + 28800)        /* 58240 */

/* ---- scratch (static device memory; allocation-free) ---- */
__device__ __align__(16) float g_s[BB*KK];
__device__ __align__(16) float g_wsym[NB*ZDIM*ZDIM];
__device__ __align__(16) float g_w2t[NB*BH];          /* bW2 transposed [t][j] */
__device__ __align__(16) float g_small[40];           /* [0..24]=wss, [28..32]=bb2+bbs */

/* ---- HOT edge-MLP weights: SEPARATE constant symbols (proven LDCU path).
   Packing into one array defeats ptxas uniform-promotion (LDC floor=8 vs
   LDCU floor=1) and doubles the edge loop. Keep split. ---- */
__constant__ __align__(16) float c_bW1[NB*BH];
__constant__ __align__(16) float c_w2t[NB*BH];
__constant__ __align__(16) float c_bb1[BH];

/* ---- f32x2 packed helpers (sm_100+) ---- */
__device__ __forceinline__ unsigned long long pk2(float lo, float hi) {
    unsigned long long r;
    asm("mov.b64 %0, {%1, %2};" : "=l"(r) : "f"(lo), "f"(hi));
    return r;
}
__device__ __forceinline__ void upk2(unsigned long long v, float& lo, float& hi) {
    asm("mov.b64 {%0, %1}, %2;" : "=f"(lo), "=f"(hi) : "l"(v));
}
__device__ __forceinline__ unsigned long long fma2(unsigned long long a,
                                                   unsigned long long b,
                                                   unsigned long long c) {
    unsigned long long r;
    asm("fma.rn.f32x2 %0, %1, %2, %3;" : "=l"(r) : "l"(a), "l"(b), "l"(c));
    return r;
}

/* lex-order edge index for pair (i<j) in a batch of NN nodes */
__device__ __forceinline__ int eidx(int i, int j) {
    return i*(2*NN - 1 - i)/2 + (j - i - 1);
}

/* -------- kernel 0: fused prep + per-batch cluster logits -------- */
__global__ void k_prep_cluster(const float* __restrict__ bm, const float* __restrict__ bW2,
                               const float* __restrict__ bWs, const float* __restrict__ bb2,
                               const float* __restrict__ bbs,
                               const float* __restrict__ eta,
                               const float* __restrict__ cW1, const float* __restrict__ cb1,
                               const float* __restrict__ cW2, const float* __restrict__ cb2,
                               const float* __restrict__ cWs, const float* __restrict__ cbs) {
    int tid = threadIdx.x;
    if (blockIdx.x >= BB) {
        int base = (blockIdx.x - BB) * CH;
        for (int i = base + tid; i < NB*ZDIM*ZDIM; i += 20*CH) {
            int t = i / (ZDIM*ZDIM);
            int r = (i / ZDIM) % ZDIM;
            int c = i % ZDIM;
            g_wsym[i] = 0.5f * (bm[t*ZDIM*ZDIM + r*ZDIM + c] +
                                bm[t*ZDIM*ZDIM + c*ZDIM + r]);
        }
        for (int i = base + tid; i < NB*BH; i += 20*CH) {
            int t = i >> 6, j = i & 63;
            g_w2t[i] = bW2[j*NB + t];
        }
        if (blockIdx.x == BB) {
            if (tid < NB*NB) g_small[tid] = bWs[tid];
            if (tid < NB)    g_small[28 + tid] = bb2[tid] + bbs[tid];
        }
        return;
    }
    __shared__ float eta_sm[ETAD];
    __shared__ float h_sm[CH];
    int b = blockIdx.x;
    if (tid < ETAD) eta_sm[tid] = eta[b*ETAD + tid];
    __syncthreads();
    float acc = cb1[tid];
    #pragma unroll 16
    for (int e = 0; e < ETAD; e++) acc = fmaf(eta_sm[e], cW1[e*CH + tid], acc);
    h_sm[tid] = fmaxf(acc, 0.f);
    __syncthreads();
    if (tid < KK) {
        float s = cb2[tid] + cbs[tid];
        #pragma unroll 16
        for (int j = 0; j < CH; j++) s = fmaf(h_sm[j], cW2[j*KK + tid], s);
        #pragma unroll 16
        for (int e = 0; e < ETAD; e++) s = fmaf(eta_sm[e], cWs[e*KK + tid], s);
        g_s[b*KK + tid] = s;
    }
}

/* -------- kernel 1: FUSED node + edge, block-per-batch, 320 threads ------ */
__global__ __launch_bounds__(TMAIN)
void k_main(const float* __restrict__ gum, const float* __restrict__ zn,
            const float* __restrict__ cm,  const float* __restrict__ cls,
            const float* __restrict__ aW1, const float* __restrict__ ab1,
            const float* __restrict__ aW2, const float* __restrict__ ab2,
            const float* __restrict__ aWs, const float* __restrict__ absk,
            float* __restrict__ atom_out, float* __restrict__ edge_out) {
    extern __shared__ __align__(16) char smraw[];
    float*  __restrict__ zs    = (float*) (smraw + SM_ZS);    /* z[j][d], ZPAD stride */
    float4* __restrict__ w1s4  = (float4*)(smraw + SM_W1);
    float*  __restrict__ aw2t  = (float*) (smraw + SM_W2T);   /* [o][j], HPADR stride */
    float*  __restrict__ awst  = (float*) (smraw + SM_WST);   /* [o][d], ZPAD stride  */
    float4* __restrict__ ab1s4 = (float4*)(smraw + SM_AB1);
    float*  __restrict__ ab2s  = (float*) (smraw + SM_AB2);
    float*  __restrict__ uni   = (float*) (smraw + SM_UNI);   /* hsm (HPADR) / vs */

    int tid  = threadIdx.x;
    int warp = tid >> 5;
    int lane = tid & 31;
    int b    = blockIdx.x;
    int nodeb = b*NN;

    /* ---- stage atom weights (padded rows) ---- */
    for (int i = tid; i < ZDIM*32; i += TMAIN) w1s4[i] = ((const float4*)aW1)[i];
    for (int i = tid; i < NA*AH;  i += TMAIN) { int o = i / AH, j = i % AH; aw2t[o*HPADR + j] = aW2[j*NA + o]; }
    for (int i = tid; i < NA*ZDIM; i += TMAIN) { int o = i / ZDIM, d = i % ZDIM; awst[o*ZPAD + d] = aWs[d*NA + o]; }
    if (tid < 32) ab1s4[tid] = ((const float4*)ab1)[tid];
    if (tid < NA) ab2s[tid]  = ab2[tid] + absk[tid];
    __syncthreads();

    /* ---- node phase 1: argmax + z (4 nodes per warp, rows 4w..4w+3) ---- */
    float srow = g_s[b*KK + lane];
    #pragma unroll
    for (int u = 0; u < 4; u++) {
        int nloc = warp*4 + u;
        int node = nodeb + nloc;
        float val = srow + gum[node*KK + lane];
        int idx = lane;
        #pragma unroll
        for (int off = 16; off; off >>= 1) {
            float ov = __shfl_xor_sync(0xffffffffu, val, off);
            int   oi = __shfl_xor_sync(0xffffffffu, idx, off);
            if (ov > val || (ov == val && oi < idx)) { val = ov; idx = oi; }
        }
        int kmax = idx;
        float ls = cls[kmax*ZDIM + lane];
        float sg = __expf(fminf(fmaxf(ls, -20.f), 30.f));
        float z  = fmaf(zn[node*ZDIM + lane], sg, cm[kmax*ZDIM + lane]);
        zs[nloc*ZPAD + lane] = z;
    }
    __syncwarp();

    /* ---- node phase 2: hidden layer (one weight load serves 4 nodes) ---- */
    {
        float4 acc0 = ab1s4[lane], acc1 = acc0, acc2 = acc0, acc3 = acc0;
        #pragma unroll
        for (int d = 0; d < ZDIM; d++) {
            float4 w = w1s4[d*32 + lane];
            float z0 = zs[(warp*4 + 0)*ZPAD + d];
            float z1 = zs[(warp*4 + 1)*ZPAD + d];
            float z2 = zs[(warp*4 + 2)*ZPAD + d];
            float z3 = zs[(warp*4 + 3)*ZPAD + d];
            acc0.x = fmaf(z0, w.x, acc0.x); acc0.y = fmaf(z0, w.y, acc0.y);
            acc0.z = fmaf(z0, w.z, acc0.z); acc0.w = fmaf(z0, w.w, acc0.w);
            acc1.x = fmaf(z1, w.x, acc1.x); acc1.y = fmaf(z1, w.y, acc1.y);
            acc1.z = fmaf(z1, w.z, acc1.z); acc1.w = fmaf(z1, w.w, acc1.w);
            acc2.x = fmaf(z2, w.x, acc2.x); acc2.y = fmaf(z2, w.y, acc2.y);
            acc2.z = fmaf(z2, w.z, acc2.z); acc2.w = fmaf(z2, w.w, acc2.w);
            acc3.x = fmaf(z3, w.x, acc3.x); acc3.y = fmaf(z3, w.y, acc3.y);
            acc3.z = fmaf(z3, w.z, acc3.z); acc3.w = fmaf(z3, w.w, acc3.w);
        }
        #define RELU4(a) { a.x=fmaxf(a.x,0.f); a.y=fmaxf(a.y,0.f); a.z=fmaxf(a.z,0.f); a.w=fmaxf(a.w,0.f); }
        RELU4(acc0) RELU4(acc1) RELU4(acc2) RELU4(acc3)
        reinterpret_cast<float4*>(uni + (warp*4 + 0)*HPADR)[lane] = acc0;
        reinterpret_cast<float4*>(uni + (warp*4 + 1)*HPADR)[lane] = acc1;
        reinterpret_cast<float4*>(uni + (warp*4 + 2)*HPADR)[lane] = acc2;
        reinterpret_cast<float4*>(uni + (warp*4 + 3)*HPADR)[lane] = acc3;
    }
    __syncwarp();

    /* ---- node phase 3: output layer (40 (node,out) pairs per warp) ---- */
    #pragma unroll
    for (int pass = 0; pass < 2; pass++) {
        int q = pass*32 + lane;
        if (q < 40) {
            int u = q / 10, o = q % 10;
            int nloc = warp*4 + u;
            float s = ab2s[o];
            const float* __restrict__ hrow = uni + nloc*HPADR;
            const float* __restrict__ wrow = aw2t + o*HPADR;
            #pragma unroll 8
            for (int j4 = 0; j4 < AH/4; j4++) {
                float4 h = *reinterpret_cast<const float4*>(&hrow[j4*4]);
                float4 w = *reinterpret_cast<const float4*>(&wrow[j4*4]);
                s = fmaf(h.x, w.x, fmaf(h.y, w.y, fmaf(h.z, w.z, fmaf(h.w, w.w, s))));
            }
            const float* __restrict__ wsrow = awst + o*ZPAD;
            #pragma unroll
            for (int d4 = 0; d4 < ZDIM/4; d4++) {
                float4 zv = *reinterpret_cast<const float4*>(&zs[nloc*ZPAD + d4*4]);
                float4 w  = *reinterpret_cast<const float4*>(&wsrow[d4*4]);
                s = fmaf(zv.x, w.x, fmaf(zv.y, w.y, fmaf(zv.z, w.z, fmaf(zv.w, w.w, s))));
            }
            atom_out[(nodeb + nloc)*NA + o] = s;
        }
    }
    __syncthreads();   /* node reads of w1s4/aw2t/hsm done -> may overwrite */

    /* ---- stage Wsym into smem over dead w1s4/aw2t regions (20480 B) ---- */
    {
        float4* __restrict__ wsymS = (float4*)(smraw + SM_W1);
        #pragma unroll
        for (int i = tid; i < NB*ZDIM*ZDIM/4; i += TMAIN)
            wsymS[i] = ((const float4*)g_wsym)[i];
    }
    __syncthreads();

    /* ---- edge phase: v[t][j][d] = sum_c Wsym[t][c][d] * z[j][c] ----
       NN*8 = 320 items == blockDim: one (j,d4) per thread; c outer so
       zc is loaded once and reused across all 5 t.                     */
    {
        float* __restrict__ vsw = uni;
        const float4* __restrict__ W = (const float4*)(smraw + SM_W1);
        int j = tid >> 3, d4 = tid & 7;
        float4 acc[NB];
        #pragma unroll
        for (int t = 0; t < NB; t++) acc[t] = make_float4(0.f, 0.f, 0.f, 0.f);
        #pragma unroll 8
        for (int c = 0; c < ZDIM; c++) {
            float zc = zs[j*ZPAD + c];
            #pragma unroll
            for (int t = 0; t < NB; t++) {
                float4 w = W[t*256 + c*8 + d4];
                acc[t].x = fmaf(zc, w.x, acc[t].x);
                acc[t].y = fmaf(zc, w.y, acc[t].y);
                acc[t].z = fmaf(zc, w.z, acc[t].z);
                acc[t].w = fmaf(zc, w.w, acc[t].w);
            }
        }
        #pragma unroll
        for (int t = 0; t < NB; t++)
            *reinterpret_cast<float4*>(&vsw[t*NN*ZPAD + j*ZPAD + d4*4]) = acc[t];
    }
    __syncthreads();

    const float* __restrict__ vs = uni;
    float* __restrict__ outb = edge_out + (size_t)b * EPB * NB;

    for (int w = tid; w < 400; w += TMAIN) {
        int i0, i1, j;
        if (w < 380) {
            int I = (int)(19.5f - sqrtf(380.25f - (float)w));
            if (I > 18) I = 18;
            if (I < 0)  I = 0;
            int c = I*(39 - I);
            if (w < c)  { I--; c = I*(39 - I); }
            else        { int c2 = (I + 1)*(38 - I); if (w >= c2) { I++; c = c2; } }
            j  = 2*I + 2 + (w - c);
            i0 = 2*I; i1 = 2*I + 1;
        } else {
            int I = w - 380;
            i0 = 2*I; i1 = 2*I; j = 2*I + 1;
        }
        int e0 = eidx(i0, j), e1 = eidx(i1, j);

        /* bilinear: v row shared across both edges */
        float bil0[NB], bil1[NB];
        #pragma unroll
        for (int t = 0; t < NB; t++) { bil0[t] = 0.f; bil1[t] = 0.f; }
        #pragma unroll
        for (int d4 = 0; d4 < 8; d4++) {
            float4 z0 = *reinterpret_cast<const float4*>(&zs[i0*ZPAD + d4*4]);
            float4 z1 = *reinterpret_cast<const float4*>(&zs[i1*ZPAD + d4*4]);
            #pragma unroll
            for (int t = 0; t < NB; t++) {
                float4 v = *reinterpret_cast<const float4*>(&vs[t*NN*ZPAD + j*ZPAD + d4*4]);
                bil0[t] = fmaf(z0.w, v.w, fmaf(z0.z, v.z, fmaf(z0.y, v.y, fmaf(z0.x, v.x, bil0[t]))));
                bil1[t] = fmaf(z1.w, v.w, fmaf(z1.z, v.z, fmaf(z1.y, v.y, fmaf(z1.x, v.x, bil1[t]))));
            }
        }

        /* skip path (cold weights via uniform global loads) + pack */
        unsigned long long oo0[NB], oo1[NB], bp0[NB], bp1[NB];
        #pragma unroll
        for (int t = 0; t < NB; t++) {
            float base = __ldg(&g_small[28 + t]);
            float s0 = base, s1 = base;
            #pragma unroll
            for (int u = 0; u < NB; u++) {
                float wv = __ldg(&g_small[u*NB + t]);
                s0 = fmaf(bil0[u], wv, s0);
                s1 = fmaf(bil1[u], wv, s1);
            }
            oo0[t] = pk2(s0, 0.f);
            oo1[t] = pk2(s1, 0.f);
            bp0[t] = pk2(bil0[t], bil0[t]);
            bp1[t] = pk2(bil1[t], bil1[t]);
        }

        /* MLP: hidden pairs, weights via uniform constant (LDCU) loads */
        #pragma unroll 4
        for (int jp = 0; jp < BH/2; jp++) {
            unsigned long long b1p =
                *reinterpret_cast<const unsigned long long*>(&c_bb1[2*jp]);
            unsigned long long h0 = b1p, h1 = b1p;
            #pragma unroll
            for (int t = 0; t < NB; t++) {
                unsigned long long w1p =
                    *reinterpret_cast<const unsigned long long*>(&c_bW1[t*BH + 2*jp]);
                h0 = fma2(bp0[t], w1p, h0);
                h1 = fma2(bp1[t], w1p, h1);
            }
            { float x, y; upk2(h0, x, y); h0 = pk2(fmaxf(x, 0.f), fmaxf(y, 0.f)); }
            { float x, y; upk2(h1, x, y); h1 = pk2(fmaxf(x, 0.f), fmaxf(y, 0.f)); }
            #pragma unroll
            for (int t = 0; t < NB; t++) {
                unsigned long long w2p =
                    *reinterpret_cast<const unsigned long long*>(&c_w2t[t*BH + 2*jp]);
                oo0[t] = fma2(h0, w2p, oo0[t]);
                oo1[t] = fma2(h1, w2p, oo1[t]);
            }
        }

        /* reduce halves, softmax, store */
        {
            float o[NB];
            #pragma unroll
            for (int t = 0; t < NB; t++) { float x, y; upk2(oo0[t], x, y); o[t] = x + y; }
            float m = o[0];
            #pragma unroll
            for (int t = 1; t < NB; t++) m = fmaxf(m, o[t]);
            float s = 0.f, ex[NB];
            #pragma unroll
            for (int t = 0; t < NB; t++) { ex[t] = __expf(o[t] - m); s += ex[t]; }
            float inv = __fdividef(1.f, s);
            #pragma unroll
            for (int t = 0; t < NB; t++) outb[e0*NB + t] = ex[t] * inv;
        }
        {
            float o[NB];
            #pragma unroll
            for (int t = 0; t < NB; t++) { float x, y; upk2(oo1[t], x, y); o[t] = x + y; }
            float m = o[0];
            #pragma unroll
            for (int t = 1; t < NB; t++) m = fmaxf(m, o[t]);
            float s = 0.f, ex[NB];
            #pragma unroll
            for (int t = 0; t < NB; t++) { ex[t] = __expf(o[t] - m); s += ex[t]; }
            float inv = __fdividef(1.f, s);
            #pragma unroll
            for (int t = 0; t < NB; t++) outb[e1*NB + t] = ex[t] * inv;
        }
    }
}

/* ------------------------- launch ------------------------- */
extern "C" void kernel_launch(void* const* d_in, const int* in_sizes, int n_in,
                              void* d_out, int out_size) {
    const float* eta  = (const float*)d_in[0];
    const float* gum  = (const float*)d_in[1];
    const float* zn   = (const float*)d_in[2];
    const float* cW1  = (const float*)d_in[3];
    const float* cb1  = (const float*)d_in[4];
    const float* cW2  = (const float*)d_in[5];
    const float* cb2  = (const float*)d_in[6];
    const float* cWs  = (const float*)d_in[7];
    const float* cbs  = (const float*)d_in[8];
    const float* cm   = (const float*)d_in[9];
    const float* cls  = (const float*)d_in[10];
    const float* aW1  = (const float*)d_in[11];
    const float* ab1  = (const float*)d_in[12];
    const float* aW2  = (const float*)d_in[13];
    const float* ab2  = (const float*)d_in[14];
    const float* aWs  = (const float*)d_in[15];
    const float* absk = (const float*)d_in[16];
    const float* bm   = (const float*)d_in[17];
    const float* bW1  = (const float*)d_in[18];
    const float* bb1  = (const float*)d_in[19];
    const float* bW2  = (const float*)d_in[20];
    const float* bb2  = (const float*)d_in[21];
    const float* bWs  = (const float*)d_in[22];
    const float* bbs  = (const float*)d_in[23];

    float* atom_out = (float*)d_out;
    float* edge_out = atom_out + (size_t)NODES * NA;

    cudaFuncSetAttribute(k_main, cudaFuncAttributeMaxDynamicSharedMemorySize, SM_TOTAL);

    /* hot edge-MLP weights -> separate constant symbols */
    cudaMemcpyToSymbolAsync(c_bW1, bW1, NB*BH*sizeof(float), 0, cudaMemcpyDeviceToDevice, 0);
    cudaMemcpyToSymbolAsync(c_bb1, bb1, BH*sizeof(float),    0, cudaMemcpyDeviceToDevice, 0);

    k_prep_cluster<<<BB + 20, CH>>>(bm, bW2, bWs, bb2, bbs,
                                    eta, cW1, cb1, cW2, cb2, cWs, cbs);

    void* w2t_ptr = nullptr;
    cudaGetSymbolAddress(&w2t_ptr, g_w2t);
    cudaMemcpyToSymbolAsync(c_w2t, w2t_ptr, NB*BH*sizeof(float), 0, cudaMemcpyDeviceToDevice, 0);

    k_main<<<BB, TMAIN, SM_TOTAL>>>(gum, zn, cm, cls, aW1, ab1, aW2, ab2, aWs, absk,
                                    atom_out, edge_out);
}